// round 15
// baseline (speedup 1.0000x reference)
#include <cuda_runtime.h>
#include <cuda_bf16.h>
#include <math.h>
#include <stdint.h>

#define T_IN  2048
#define F_DIM 256
#define H_DIM 384
#define TP    2051
#define MPAD  2176            // 17 * 128
#define NTOT  1536            // 4 projections * 384
#define TB    384             // b-stride of (t,b) activations
#define NCH   129             // scan chunks
#define CH    16              // t per scan chunk
#define INV_SQRT_H 0.05103103703f

// ---------------- scratch (zero-initialized device globals) ------------------
__device__ __align__(16) __nv_bfloat16 g_ah[MPAD * F_DIM];  // xp hi (pad rows 0)
__device__ __align__(16) __nv_bfloat16 g_al[MPAD * F_DIM];  // xp lo
__device__ __align__(16) __nv_bfloat16 g_bh[NTOT * F_DIM];  // W  hi (k,v,i,f)
__device__ __align__(16) __nv_bfloat16 g_bl[NTOT * F_DIM];  // W  lo
__device__ __align__(16) float g_kb [TP * TB];   // (t,b)
__device__ __align__(16) float g_vb [TP * TB];
__device__ __align__(16) float g_zib[TP * TB];
__device__ __align__(16) float g_lfb[TP * TB];
__device__ __align__(16) float g_cs  [NCH * TB]; // raw chunk sums of log f
__device__ __align__(16) float g_zmax[NCH * TB]; // per-chunk max of zi (live tiles)
__device__ __align__(16) float g_sfx [NCH * TB]; // exclusive suffix of chunk sums
__device__ __align__(16) float g_part[NCH * TB]; // per-chunk partial dots
__device__ float g_wsum[NCH];
__device__ float g_qT[H_DIM];
__device__ float g_oT[H_DIM];
__device__ float g_xn2max[NCH];   // per-chunk max ||xp_t||^2 (atomicMax, idempotent)
__device__ float g_win[TB];       // ||Wi_b||_2
__device__ int   g_livec[NCH];    // chunk liveness by bound

// ---------------- PTX helpers (baseline sm_80+, compile for sm_103) ---------
__device__ __forceinline__ uint32_t smem_u32(const void* p) {
    uint32_t a;
    asm("{ .reg .u64 t; cvta.to.shared.u64 t, %1; cvt.u32.u64 %0, t; }"
        : "=r"(a) : "l"(p));
    return a;
}
#define LDSM4(r0, r1, r2, r3, addr) \
    asm volatile("ldmatrix.sync.aligned.m8n8.x4.shared.b16 {%0,%1,%2,%3}, [%4];" \
                 : "=r"(r0), "=r"(r1), "=r"(r2), "=r"(r3) : "r"(addr))
#define MMA16816(d, a, b) \
    asm volatile("mma.sync.aligned.m16n8k16.row.col.f32.bf16.bf16.f32 " \
                 "{%0,%1,%2,%3},{%4,%5,%6,%7},{%8,%9},{%0,%1,%2,%3};" \
                 : "+f"((d)[0]), "+f"((d)[1]), "+f"((d)[2]), "+f"((d)[3]) \
                 : "r"((a)[0]), "r"((a)[1]), "r"((a)[2]), "r"((a)[3]), \
                   "r"((b)[0]), "r"((b)[1]))
#define CP_ASYNC16(dst, src) \
    asm volatile("cp.async.cg.shared.global [%0], [%1], 16;" \
                 :: "r"(dst), "l"(src) : "memory")
#define CP_COMMIT() asm volatile("cp.async.commit_group;" ::: "memory")
#define CP_WAIT(n)  asm volatile("cp.async.wait_group %0;" :: "n"(n) : "memory")

// ---------------- 1. prep: conv+split | W split | q/o GEMV | Wi norms --------
#define NB_CONV 513
#define NB_CVTB 384
#define NB_QO   96
#define NB_WIN  48

__global__ void prep(const float* __restrict__ x,
                     const float* __restrict__ cw, const float* __restrict__ cb,
                     const float* __restrict__ Wq, const float* __restrict__ bq,
                     const float* __restrict__ Wo, const float* __restrict__ bo,
                     const float* __restrict__ Wk, const float* __restrict__ Wv,
                     const float* __restrict__ Wi, const float* __restrict__ Wf) {
    const int blk = blockIdx.x;
    const int tid = threadIdx.x;
    if (blk < NB_CONV) {
        int idx = blk * 256 + tid;
        int t = idx >> 6, qf = (idx & 63) * 4;
        bool ok = (idx < TP * (F_DIM / 4));
        float ss = 0.f;
        if (ok) {
            float b0 = cb[0];
            float4 acc = make_float4(b0, b0, b0, b0);
#pragma unroll
            for (int j = 0; j < 4; ++j) {
                int s = t + j - 3;
                if (s >= 0 && s < T_IN) {
                    float4 xv = *reinterpret_cast<const float4*>(&x[s * F_DIM + qf]);
                    float w = cw[j];
                    acc.x = fmaf(w, xv.x, acc.x); acc.y = fmaf(w, xv.y, acc.y);
                    acc.z = fmaf(w, xv.z, acc.z); acc.w = fmaf(w, xv.w, acc.w);
                }
            }
            float vv[4] = {acc.x, acc.y, acc.z, acc.w};
            ss = acc.x * acc.x + acc.y * acc.y + acc.z * acc.z + acc.w * acc.w;
            __nv_bfloat16 hi[4], lo[4];
#pragma unroll
            for (int e = 0; e < 4; ++e) {
                hi[e] = __float2bfloat16_rn(vv[e]);
                lo[e] = __float2bfloat16_rn(vv[e] - __bfloat162float(hi[e]));
            }
            size_t o = (size_t)t * F_DIM + qf;
            *reinterpret_cast<__nv_bfloat162*>(&g_ah[o])     = __nv_bfloat162(hi[0], hi[1]);
            *reinterpret_cast<__nv_bfloat162*>(&g_ah[o + 2]) = __nv_bfloat162(hi[2], hi[3]);
            *reinterpret_cast<__nv_bfloat162*>(&g_al[o])     = __nv_bfloat162(lo[0], lo[1]);
            *reinterpret_cast<__nv_bfloat162*>(&g_al[o + 2]) = __nv_bfloat162(lo[2], lo[3]);
        }
        // per-t ||xp||^2 over 64 threads (2 warps), then chunk max
        __shared__ float sq[4];
        if (tid < 4) sq[tid] = 0.f;
        __syncthreads();
#pragma unroll
        for (int off = 16; off; off >>= 1) ss += __shfl_xor_sync(0xffffffffu, ss, off);
        if ((tid & 31) == 0) atomicAdd(&sq[tid >> 6], ss);
        __syncthreads();
        if ((tid & 63) == 0 && ok)
            atomicMax(reinterpret_cast<int*>(&g_xn2max[t / CH]),
                      __float_as_int(sq[tid >> 6]));
    } else if (blk < NB_CONV + NB_CVTB) {
        int idx = (blk - NB_CONV) * 256 + tid;
        int n = idx >> 6, qf = (idx & 63) * 4;
        int proj = n / H_DIM, r = n % H_DIM;
        const float* W = (proj == 0) ? Wk : (proj == 1) ? Wv : (proj == 2) ? Wi : Wf;
        float4 w = *reinterpret_cast<const float4*>(&W[r * F_DIM + qf]);
        float vv[4] = {w.x, w.y, w.z, w.w};
        __nv_bfloat16 hi[4], lo[4];
#pragma unroll
        for (int e = 0; e < 4; ++e) {
            hi[e] = __float2bfloat16_rn(vv[e]);
            lo[e] = __float2bfloat16_rn(vv[e] - __bfloat162float(hi[e]));
        }
        size_t o = (size_t)n * F_DIM + qf;
        *reinterpret_cast<__nv_bfloat162*>(&g_bh[o])     = __nv_bfloat162(hi[0], hi[1]);
        *reinterpret_cast<__nv_bfloat162*>(&g_bh[o + 2]) = __nv_bfloat162(hi[2], hi[3]);
        *reinterpret_cast<__nv_bfloat162*>(&g_bl[o])     = __nv_bfloat162(lo[0], lo[1]);
        *reinterpret_cast<__nv_bfloat162*>(&g_bl[o + 2]) = __nv_bfloat162(lo[2], lo[3]);
    } else if (blk < NB_CONV + NB_CVTB + NB_QO) {
        int j = blk - NB_CONV - NB_CVTB;
        int type = j & 1, bx = j >> 1;
        int warp = tid >> 5, lane = tid & 31;
        int b = bx * 8 + warp;
        const float* W  = type ? Wo : Wq;
        const float* bb = type ? bo : bq;
        float cw0 = cw[0], cb0 = cb[0];
        const float* xr = &x[(size_t)2047 * F_DIM];
        float s = 0.f;
        for (int f = lane; f < F_DIM; f += 32)
            s = fmaf(W[b * F_DIM + f], fmaf(cw0, xr[f], cb0), s);
#pragma unroll
        for (int off = 16; off; off >>= 1) s += __shfl_xor_sync(0xffffffffu, s, off);
        if (lane == 0) {
            float z = s + bb[b];
            if (type) g_oT[b] = 1.f / (1.f + expf(-z));
            else      g_qT[b] = z;
        }
    } else {
        // ||Wi_b||_2 for the zi bound
        int j = blk - NB_CONV - NB_CVTB - NB_QO;
        int warp = tid >> 5, lane = tid & 31;
        int b = j * 8 + warp;
        float s = 0.f;
        for (int f = lane; f < F_DIM; f += 32) {
            float w = Wi[b * F_DIM + f];
            s = fmaf(w, w, s);
        }
#pragma unroll
        for (int off = 16; off; off >>= 1) s += __shfl_xor_sync(0xffffffffu, s, off);
        if (lane == 0) g_win[b] = sqrtf(s);
    }
}

// ---------------- 2. split-bf16x3 GEMM + fused epilogue reductions -----------
// proj = proj_base + (blockIdx.y >> 1); check_live: skip M-tiles with no live chunk.
#define RS      80
#define AH_OFF  0
#define AL_OFF  10240
#define BH_OFF  20480
#define BL_OFF  35840
#define BUF     51200
#define SMEM_GEMM (2 * BUF)   // 102400

__global__ void __launch_bounds__(384, 1)
mma_gemm(const float* __restrict__ bk, const float* __restrict__ bv,
         const float* __restrict__ bi, const float* __restrict__ bf_,
         int proj_base, int check_live) {
    if (check_live) {
        int alive = 0;
#pragma unroll
        for (int i = 0; i < 8; ++i) {
            int c = blockIdx.x * 8 + i;
            if (c < NCH) alive |= g_livec[c];
        }
        if (!alive) return;
    }
    extern __shared__ char sm[];
    const uint32_t sb = smem_u32(sm);
    const int tid = threadIdx.x;
    const int lane = tid & 31, wid = tid >> 5;
    const int wm = wid & 1, wn = wid >> 1;          // 2 x 6 warp grid
    const int t0 = blockIdx.x * 128;
    const int proj = proj_base + (blockIdx.y >> 1);
    const int cbase = (blockIdx.y & 1) * 192;
    const int n0g = proj * H_DIM + cbase;

    float acc[4][4][4];
#pragma unroll
    for (int i = 0; i < 4; ++i)
#pragma unroll
        for (int jj = 0; jj < 4; ++jj)
#pragma unroll
            for (int e = 0; e < 4; ++e) acc[i][jj][e] = 0.f;

    const uint32_t aOff = (uint32_t)(wm * 64 + (lane & 15)) * RS + ((lane >> 4) * 16);
    const uint32_t bOff = (uint32_t)(wn * 32 + ((lane >> 4) << 3) + (lane & 7)) * RS
                        + (((lane >> 3) & 1) * 16);

    auto issue_chunk = [&](int kc, int buf) {
        uint32_t dst = sb + (uint32_t)buf * BUF;
        for (int u = tid; u < 512; u += 384) {
            int row = u >> 2, c = u & 3;
            uint32_t a = (uint32_t)row * RS + c * 16;
            size_t g = (size_t)(t0 + row) * F_DIM + kc * 32 + c * 8;
            CP_ASYNC16(dst + AH_OFF + a, &g_ah[g]);
            CP_ASYNC16(dst + AL_OFF + a, &g_al[g]);
        }
        for (int u = tid; u < 768; u += 384) {
            int row = u >> 2, c = u & 3;
            uint32_t a = (uint32_t)row * RS + c * 16;
            size_t g = (size_t)(n0g + row) * F_DIM + kc * 32 + c * 8;
            CP_ASYNC16(dst + BH_OFF + a, &g_bh[g]);
            CP_ASYNC16(dst + BL_OFF + a, &g_bl[g]);
        }
        CP_COMMIT();
    };

    issue_chunk(0, 0);
    for (int kc = 0; kc < 8; ++kc) {
        if (kc < 7) { issue_chunk(kc + 1, (kc + 1) & 1); CP_WAIT(1); }
        else        { CP_WAIT(0); }
        __syncthreads();
        const uint32_t base = sb + (uint32_t)(kc & 1) * BUF;
#pragma unroll
        for (int ks = 0; ks < 2; ++ks) {
            uint32_t ah[4][4], al[4][4], bh[4][2], bl[4][2];
            uint32_t aH = base + AH_OFF + aOff + ks * 32;
            uint32_t aL = base + AL_OFF + aOff + ks * 32;
            uint32_t bH = base + BH_OFF + bOff + ks * 32;
            uint32_t bL = base + BL_OFF + bOff + ks * 32;
#pragma unroll
            for (int mt = 0; mt < 4; ++mt)
                LDSM4(ah[mt][0], ah[mt][1], ah[mt][2], ah[mt][3], aH + mt * 16 * RS);
            LDSM4(bh[0][0], bh[0][1], bh[1][0], bh[1][1], bH);
            LDSM4(bh[2][0], bh[2][1], bh[3][0], bh[3][1], bH + 16 * RS);
#pragma unroll
            for (int mt = 0; mt < 4; ++mt)
                LDSM4(al[mt][0], al[mt][1], al[mt][2], al[mt][3], aL + mt * 16 * RS);
            LDSM4(bl[0][0], bl[0][1], bl[1][0], bl[1][1], bL);
            LDSM4(bl[2][0], bl[2][1], bl[3][0], bl[3][1], bL + 16 * RS);
#pragma unroll
            for (int mt = 0; mt < 4; ++mt)
#pragma unroll
                for (int nt = 0; nt < 4; ++nt)
                    MMA16816(acc[mt][nt], ah[mt], bh[nt]);
#pragma unroll
            for (int mt = 0; mt < 4; ++mt)
#pragma unroll
                for (int nt = 0; nt < 4; ++nt)
                    MMA16816(acc[mt][nt], ah[mt], bl[nt]);
#pragma unroll
            for (int mt = 0; mt < 4; ++mt)
#pragma unroll
                for (int nt = 0; nt < 4; ++nt)
                    MMA16816(acc[mt][nt], al[mt], bh[nt]);
        }
        __syncthreads();
    }

    // ---- epilogue: bias + activation, store (t,b); fused chunk reductions ----
    const float* bias = (proj == 0) ? bk : (proj == 1) ? bv : (proj == 2) ? bi : bf_;
    float* outp = (proj == 0) ? g_kb : (proj == 1) ? g_vb : (proj == 2) ? g_zib : g_lfb;
    const int g = lane >> 2, tq = lane & 3;
#pragma unroll
    for (int nt = 0; nt < 4; ++nt) {
        int col = cbase + wn * 32 + nt * 8 + tq * 2;
        float2 b2 = *reinterpret_cast<const float2*>(&bias[col]);
#pragma unroll
        for (int mt = 0; mt < 4; ++mt) {
            float red0, red1;                     // sum (proj3) / max (proj2)
            if (proj == 2) { red0 = -1e30f; red1 = -1e30f; }
            else           { red0 = 0.f;    red1 = 0.f; }
#pragma unroll
            for (int half = 0; half < 2; ++half) {
                int trow = t0 + wm * 64 + mt * 16 + g + half * 8;
                bool valid = (trow < TP);
                float e0 = acc[mt][nt][half * 2 + 0] + b2.x;
                float e1 = acc[mt][nt][half * 2 + 1] + b2.y;
                if (proj == 0) { e0 *= INV_SQRT_H; e1 *= INV_SQRT_H; }
                else if (proj == 3) {
                    e0 = fminf(e0, 0.f) - log1pf(__expf(-fabsf(e0)));
                    e1 = fminf(e1, 0.f) - log1pf(__expf(-fabsf(e1)));
                }
                if (valid)
                    *reinterpret_cast<float2*>(&outp[(size_t)trow * TB + col]) =
                        make_float2(e0, e1);
                if (proj == 3) {
                    red0 += valid ? e0 : 0.f;
                    red1 += valid ? e1 : 0.f;
                } else if (proj == 2) {
                    red0 = valid ? fmaxf(red0, e0) : red0;
                    red1 = valid ? fmaxf(red1, e1) : red1;
                }
            }
            if (proj == 3) {                      // chunk sum of lf -> g_cs
#pragma unroll
                for (int off = 4; off <= 16; off <<= 1) {
                    red0 += __shfl_xor_sync(0xffffffffu, red0, off);
                    red1 += __shfl_xor_sync(0xffffffffu, red1, off);
                }
                int c = blockIdx.x * 8 + wm * 4 + mt;
                if (g == 0 && c < NCH) {
                    g_cs[c * TB + col]     = red0;
                    g_cs[c * TB + col + 1] = red1;
                }
            } else if (proj == 2) {               // chunk max of zi -> g_zmax
#pragma unroll
                for (int off = 4; off <= 16; off <<= 1) {
                    red0 = fmaxf(red0, __shfl_xor_sync(0xffffffffu, red0, off));
                    red1 = fmaxf(red1, __shfl_xor_sync(0xffffffffu, red1, off));
                }
                int c = blockIdx.x * 8 + wm * 4 + mt;
                if (g == 0 && c < NCH) {
                    g_zmax[c * TB + col]     = red0;
                    g_zmax[c * TB + col + 1] = red1;
                }
            }
        }
    }
}

// ---------------- 3. suffix over chunks: one BLOCK per b ----------------------
__global__ void __launch_bounds__(256)
s2_chunkscan() {
    const int b = blockIdx.x;
    const int t = threadIdx.x;
    __shared__ float sv[256];
    float v = (t < NCH) ? g_cs[t * TB + b] : 0.f;
    sv[t] = v;
    __syncthreads();
#pragma unroll
    for (int d = 1; d < 256; d <<= 1) {
        float add = (t + d < 256) ? sv[t + d] : 0.f;
        __syncthreads();
        sv[t] += add;
        __syncthreads();
    }
    if (t < NCH) {
        float run = (t + 1 < 256) ? sv[t + 1] : 0.f;  // exclusive suffix
        g_sfx[t * TB + b] = run;
    }
}

// ---------------- 4. chunk liveness by Cauchy-Schwarz bound ------------------
__global__ void __launch_bounds__(TB)
live_kernel(const float* __restrict__ bi) {
    const int c = blockIdx.x, b = threadIdx.x;
    float xn = sqrtf(g_xn2max[c]);
    float bound = xn * g_win[b] + bi[b] + 2.0f;     // >= max zi in chunk (+margin)
    int lv = (bound + g_sfx[c * TB + b] > -85.f) ? 1 : 0;
    int any = __syncthreads_or(lv);
    if (b == 0) g_livec[c] = any;
}

// ---------------- 5. contribs + w + partial dots (live chunks only) ----------
__global__ void __launch_bounds__(TB)
s3_contrib() {
    const int b = threadIdx.x, c = blockIdx.x;
    const int wid = b >> 5, lid = b & 31;
    __shared__ float Cs[CH][TB + 1];
    __shared__ float ws[CH];

    if (!g_livec[c]) {                             // uniform branch, no sync
        g_part[c * TB + b] = 0.f;
        if (b == 0) g_wsum[c] = 0.f;
        return;
    }

    float suffix = g_sfx[c * TB + b];
    float zm     = g_zmax[c * TB + b];
    bool live = (zm + suffix > -85.f);

    // front-batched independent loads
    const int tbase = c * CH;
    float zi_r[CH], kk_r[CH], lf_r[CH], vv_r[CH];
#pragma unroll
    for (int i = 0; i < CH; ++i) {
        int t = tbase + i;
        int tc = (t < TP) ? t : (TP - 1);
        size_t o = (size_t)tc * TB + b;
        zi_r[i] = g_zib[o];
        kk_r[i] = g_kb[o];
        lf_r[i] = g_lfb[o];
        vv_r[i] = g_vb[o];
    }

    float qb = g_qT[b];
    float run = suffix;
#pragma unroll
    for (int i = CH - 1; i >= 0; --i) {
        float cv = 0.f;
        if (tbase + i < TP) {
            if (live) {
                float zr = zi_r[i] + run;
                if (zr > -85.f) cv = __expf(zr) * kk_r[i] * qb;
            }
            run += lf_r[i];
        }
        Cs[i][b] = cv;
    }
    __syncthreads();
#pragma unroll
    for (int p = 0; p < 2; ++p) {
        int i = p * 12 + wid;
        if (i < CH) {
            float s = 0.f;
#pragma unroll
            for (int jj = lid; jj < TB; jj += 32) s += Cs[i][jj];
#pragma unroll
            for (int off = 16; off; off >>= 1) s += __shfl_xor_sync(0xffffffffu, s, off);
            if (lid == 0) ws[i] = s;
        }
    }
    __syncthreads();
    float pnum = 0.f;
#pragma unroll
    for (int i = 0; i < CH; ++i)
        if (tbase + i < TP) pnum = fmaf(vv_r[i], ws[i], pnum);
    g_part[c * TB + b] = pnum;
    if (b == 0) {
        float s = 0.f;
#pragma unroll
        for (int i = 0; i < CH; ++i) s += ws[i];
        g_wsum[c] = s;
    }
}

// ---------------- 6. combine: h[a] --------------------------------------------
__global__ void __launch_bounds__(TB)
f2_combine(float* __restrict__ out) {
    int a = threadIdx.x;
    float num = 0.f, den = 0.f;
#pragma unroll 8
    for (int c = 0; c < NCH; ++c) num += g_part[c * TB + a];
#pragma unroll 8
    for (int c = 0; c < NCH; ++c) den += g_wsum[c];
    out[a] = g_oT[a] * num / fmaxf(fabsf(den), 1.0f);
}

// -----------------------------------------------------------------------------
extern "C" void kernel_launch(void* const* d_in, const int* in_sizes, int n_in,
                              void* d_out, int out_size) {
    const float* x  = (const float*)d_in[0];
    const float* Wq = (const float*)d_in[1];  const float* bq = (const float*)d_in[2];
    const float* Wk = (const float*)d_in[3];  const float* bk = (const float*)d_in[4];
    const float* Wv = (const float*)d_in[5];  const float* bv = (const float*)d_in[6];
    const float* Wi = (const float*)d_in[7];  const float* bi = (const float*)d_in[8];
    const float* Wf = (const float*)d_in[9];  const float* bf = (const float*)d_in[10];
    const float* Wo = (const float*)d_in[11]; const float* bo = (const float*)d_in[12];
    const float* cw = (const float*)d_in[13]; const float* cb = (const float*)d_in[14];
    float* out = (float*)d_out;

    static int smem_set = 0;
    if (!smem_set) {
        cudaFuncSetAttribute(mma_gemm, cudaFuncAttributeMaxDynamicSharedMemorySize,
                             SMEM_GEMM);
        smem_set = 1;
    }

    prep<<<NB_CONV + NB_CVTB + NB_QO + NB_WIN, 256>>>(x, cw, cb, Wq, bq, Wo, bo,
                                                      Wk, Wv, Wi, Wf);
    // f projection (lf) over full range; writes g_lfb + chunk sums g_cs
    mma_gemm<<<dim3(MPAD / 128, 2), 384, SMEM_GEMM>>>(bk, bv, bi, bf, 3, 0);
    s2_chunkscan<<<TB, 256>>>();
    live_kernel<<<NCH, TB>>>(bi);
    // k, v, zi projections only on live M-tiles
    mma_gemm<<<dim3(MPAD / 128, 6), 384, SMEM_GEMM>>>(bk, bv, bi, bf, 0, 1);
    s3_contrib<<<NCH, TB>>>();
    f2_combine<<<1, TB>>>(out);
}

// round 16
// speedup vs baseline: 1.6593x; 1.6593x over previous
#include <cuda_runtime.h>
#include <cuda_fp16.h>
#include <math.h>
#include <stdint.h>

#define T_IN  2048
#define F_DIM 256
#define H_DIM 384
#define TP    2051
#define MPAD  2176            // 17 * 128
#define NTOT  1536            // 4 projections * 384
#define TB    384             // b-stride of (t,b) activations
#define NCH   129             // scan chunks
#define CH    16              // t per scan chunk
#define INV_SQRT_H 0.05103103703f

// ---------------- scratch (zero-initialized device globals) ------------------
__device__ __align__(16) __half g_ah[MPAD * F_DIM];   // xp fp16 (pad rows 0)
__device__ __align__(16) __half g_bh[NTOT * F_DIM];   // W hi fp16 (k,v,i,f)
__device__ __align__(16) __half g_bl[NTOT * F_DIM];   // W lo fp16
__device__ __align__(16) float g_kb [TP * TB];   // (t,b)
__device__ __align__(16) float g_vb [TP * TB];
__device__ __align__(16) float g_zib[TP * TB];
__device__ __align__(16) float g_lfb[TP * TB];
__device__ __align__(16) float g_cs  [NCH * TB]; // raw chunk sums of log f
__device__ __align__(16) float g_zmax[NCH * TB]; // per-chunk max of zi
__device__ __align__(16) float g_sfx [NCH * TB]; // exclusive suffix of chunk sums
__device__ __align__(16) float g_part[NCH * TB]; // per-chunk partial dots
__device__ float g_wsum[NCH];
__device__ float g_qT[H_DIM];
__device__ float g_oT[H_DIM];

// ---------------- PTX helpers (baseline sm_80+, compile for sm_103) ---------
__device__ __forceinline__ uint32_t smem_u32(const void* p) {
    uint32_t a;
    asm("{ .reg .u64 t; cvta.to.shared.u64 t, %1; cvt.u32.u64 %0, t; }"
        : "=r"(a) : "l"(p));
    return a;
}
#define LDSM4(r0, r1, r2, r3, addr) \
    asm volatile("ldmatrix.sync.aligned.m8n8.x4.shared.b16 {%0,%1,%2,%3}, [%4];" \
                 : "=r"(r0), "=r"(r1), "=r"(r2), "=r"(r3) : "r"(addr))
#define MMAF16(d, a, b) \
    asm volatile("mma.sync.aligned.m16n8k16.row.col.f32.f16.f16.f32 " \
                 "{%0,%1,%2,%3},{%4,%5,%6,%7},{%8,%9},{%0,%1,%2,%3};" \
                 : "+f"((d)[0]), "+f"((d)[1]), "+f"((d)[2]), "+f"((d)[3]) \
                 : "r"((a)[0]), "r"((a)[1]), "r"((a)[2]), "r"((a)[3]), \
                   "r"((b)[0]), "r"((b)[1]))
#define CP_ASYNC16(dst, src) \
    asm volatile("cp.async.cg.shared.global [%0], [%1], 16;" \
                 :: "r"(dst), "l"(src) : "memory")
#define CP_COMMIT() asm volatile("cp.async.commit_group;" ::: "memory")
#define CP_WAIT(n)  asm volatile("cp.async.wait_group %0;" :: "n"(n) : "memory")

// ---------------- 1. fused prep: conv->fp16 | W split fp16 | q/o GEMV --------
#define NB_CONV 513
#define NB_CVTB 384
#define NB_QO   96

__global__ void prep(const float* __restrict__ x,
                     const float* __restrict__ cw, const float* __restrict__ cb,
                     const float* __restrict__ Wq, const float* __restrict__ bq,
                     const float* __restrict__ Wo, const float* __restrict__ bo,
                     const float* __restrict__ Wk, const float* __restrict__ Wv,
                     const float* __restrict__ Wi, const float* __restrict__ Wf) {
    const int blk = blockIdx.x;
    if (blk < NB_CONV) {
        int idx = blk * 256 + threadIdx.x;
        if (idx >= TP * (F_DIM / 4)) return;
        int t = idx >> 6, qf = (idx & 63) * 4;
        float b0 = cb[0];
        float4 acc = make_float4(b0, b0, b0, b0);
#pragma unroll
        for (int j = 0; j < 4; ++j) {
            int s = t + j - 3;
            if (s >= 0 && s < T_IN) {
                float4 xv = *reinterpret_cast<const float4*>(&x[s * F_DIM + qf]);
                float w = cw[j];
                acc.x = fmaf(w, xv.x, acc.x); acc.y = fmaf(w, xv.y, acc.y);
                acc.z = fmaf(w, xv.z, acc.z); acc.w = fmaf(w, xv.w, acc.w);
            }
        }
        size_t o = (size_t)t * F_DIM + qf;
        *reinterpret_cast<__half2*>(&g_ah[o])     = __floats2half2_rn(acc.x, acc.y);
        *reinterpret_cast<__half2*>(&g_ah[o + 2]) = __floats2half2_rn(acc.z, acc.w);
    } else if (blk < NB_CONV + NB_CVTB) {
        int idx = (blk - NB_CONV) * 256 + threadIdx.x;
        int n = idx >> 6, qf = (idx & 63) * 4;
        int proj = n / H_DIM, r = n % H_DIM;
        const float* W = (proj == 0) ? Wk : (proj == 1) ? Wv : (proj == 2) ? Wi : Wf;
        float4 w = *reinterpret_cast<const float4*>(&W[r * F_DIM + qf]);
        float vv[4] = {w.x, w.y, w.z, w.w};
        __half hi[4], lo[4];
#pragma unroll
        for (int e = 0; e < 4; ++e) {
            hi[e] = __float2half_rn(vv[e]);
            lo[e] = __float2half_rn(vv[e] - __half2float(hi[e]));
        }
        size_t o = (size_t)n * F_DIM + qf;
        *reinterpret_cast<__half2*>(&g_bh[o])     = __halves2half2(hi[0], hi[1]);
        *reinterpret_cast<__half2*>(&g_bh[o + 2]) = __halves2half2(hi[2], hi[3]);
        *reinterpret_cast<__half2*>(&g_bl[o])     = __halves2half2(lo[0], lo[1]);
        *reinterpret_cast<__half2*>(&g_bl[o + 2]) = __halves2half2(lo[2], lo[3]);
    } else {
        int j = blk - NB_CONV - NB_CVTB;
        int type = j & 1, bx = j >> 1;
        int warp = threadIdx.x >> 5, lane = threadIdx.x & 31;
        int b = bx * 8 + warp;
        const float* W  = type ? Wo : Wq;
        const float* bb = type ? bo : bq;
        float cw0 = cw[0], cb0 = cb[0];
        const float* xr = &x[(size_t)2047 * F_DIM];
        float s = 0.f;
        for (int f = lane; f < F_DIM; f += 32)
            s = fmaf(W[b * F_DIM + f], fmaf(cw0, xr[f], cb0), s);
#pragma unroll
        for (int off = 16; off; off >>= 1) s += __shfl_xor_sync(0xffffffffu, s, off);
        if (lane == 0) {
            float z = s + bb[b];
            if (type) g_oT[b] = 1.f / (1.f + expf(-z));
            else      g_qT[b] = z;
        }
    }
}

// ---------------- 2. fp16 A x (Bh+Bl) GEMM + fused s1 reductions -------------
// Tile 128(M) x 192(N), 384 threads (12 warps, 2m x 6n), 2-stage cp.async.
#define RS      80
#define AH_OFF  0
#define BH_OFF  10240
#define BL_OFF  25600
#define BUF     40960
#define SMEM_GEMM (2 * BUF)   // 81920

__global__ void __launch_bounds__(384, 1)
mma_gemm(const float* __restrict__ bk, const float* __restrict__ bv,
         const float* __restrict__ bi, const float* __restrict__ bf_) {
    extern __shared__ char sm[];
    const uint32_t sb = smem_u32(sm);
    const int tid = threadIdx.x;
    const int lane = tid & 31, wid = tid >> 5;
    const int wm = wid & 1, wn = wid >> 1;          // 2 x 6 warp grid
    const int t0 = blockIdx.x * 128, n0g = blockIdx.y * 192;

    float acc[4][4][4];
#pragma unroll
    for (int i = 0; i < 4; ++i)
#pragma unroll
        for (int jj = 0; jj < 4; ++jj)
#pragma unroll
            for (int e = 0; e < 4; ++e) acc[i][jj][e] = 0.f;

    const uint32_t aOff = (uint32_t)(wm * 64 + (lane & 15)) * RS + ((lane >> 4) * 16);
    const uint32_t bOff = (uint32_t)(wn * 32 + ((lane >> 4) << 3) + (lane & 7)) * RS
                        + (((lane >> 3) & 1) * 16);

    auto issue_chunk = [&](int kc, int buf) {
        uint32_t dst = sb + (uint32_t)buf * BUF;
        for (int u = tid; u < 512; u += 384) {      // A: 128 rows x 4 x 16B
            int row = u >> 2, c = u & 3;
            uint32_t a = (uint32_t)row * RS + c * 16;
            size_t g = (size_t)(t0 + row) * F_DIM + kc * 32 + c * 8;
            CP_ASYNC16(dst + AH_OFF + a, &g_ah[g]);
        }
        for (int u = tid; u < 768; u += 384) {      // B: 192 rows x 4 x 16B, hi+lo
            int row = u >> 2, c = u & 3;
            uint32_t a = (uint32_t)row * RS + c * 16;
            size_t g = (size_t)(n0g + row) * F_DIM + kc * 32 + c * 8;
            CP_ASYNC16(dst + BH_OFF + a, &g_bh[g]);
            CP_ASYNC16(dst + BL_OFF + a, &g_bl[g]);
        }
        CP_COMMIT();
    };

    issue_chunk(0, 0);
    for (int kc = 0; kc < 8; ++kc) {
        if (kc < 7) { issue_chunk(kc + 1, (kc + 1) & 1); CP_WAIT(1); }
        else        { CP_WAIT(0); }
        __syncthreads();
        const uint32_t base = sb + (uint32_t)(kc & 1) * BUF;
#pragma unroll
        for (int ks = 0; ks < 2; ++ks) {
            uint32_t ah[4][4], bh[4][2], bl[4][2];
            uint32_t aH = base + AH_OFF + aOff + ks * 32;
            uint32_t bH = base + BH_OFF + bOff + ks * 32;
            uint32_t bL = base + BL_OFF + bOff + ks * 32;
#pragma unroll
            for (int mt = 0; mt < 4; ++mt)
                LDSM4(ah[mt][0], ah[mt][1], ah[mt][2], ah[mt][3], aH + mt * 16 * RS);
            LDSM4(bh[0][0], bh[0][1], bh[1][0], bh[1][1], bH);
            LDSM4(bh[2][0], bh[2][1], bh[3][0], bh[3][1], bH + 16 * RS);
            LDSM4(bl[0][0], bl[0][1], bl[1][0], bl[1][1], bL);
            LDSM4(bl[2][0], bl[2][1], bl[3][0], bl[3][1], bL + 16 * RS);
#pragma unroll
            for (int mt = 0; mt < 4; ++mt)
#pragma unroll
                for (int nt = 0; nt < 4; ++nt)
                    MMAF16(acc[mt][nt], ah[mt], bh[nt]);
#pragma unroll
            for (int mt = 0; mt < 4; ++mt)
#pragma unroll
                for (int nt = 0; nt < 4; ++nt)
                    MMAF16(acc[mt][nt], ah[mt], bl[nt]);
        }
        __syncthreads();
    }

    // ---- epilogue: bias + activation, store (t,b); fused chunk reductions ----
    const int proj = n0g / H_DIM;
    const int cbase = n0g % H_DIM;
    const float* bias = (proj == 0) ? bk : (proj == 1) ? bv : (proj == 2) ? bi : bf_;
    float* outp = (proj == 0) ? g_kb : (proj == 1) ? g_vb : (proj == 2) ? g_zib : g_lfb;
    const int g = lane >> 2, tq = lane & 3;
#pragma unroll
    for (int nt = 0; nt < 4; ++nt) {
        int col = cbase + wn * 32 + nt * 8 + tq * 2;
        float2 b2 = *reinterpret_cast<const float2*>(&bias[col]);
#pragma unroll
        for (int mt = 0; mt < 4; ++mt) {
            float red0, red1;                     // sum (proj3) / max (proj2)
            if (proj == 2) { red0 = -1e30f; red1 = -1e30f; }
            else           { red0 = 0.f;    red1 = 0.f; }
#pragma unroll
            for (int half = 0; half < 2; ++half) {
                int trow = t0 + wm * 64 + mt * 16 + g + half * 8;
                bool valid = (trow < TP);
                float e0 = acc[mt][nt][half * 2 + 0] + b2.x;
                float e1 = acc[mt][nt][half * 2 + 1] + b2.y;
                if (proj == 0) { e0 *= INV_SQRT_H; e1 *= INV_SQRT_H; }
                else if (proj == 3) {
                    e0 = fminf(e0, 0.f) - log1pf(__expf(-fabsf(e0)));
                    e1 = fminf(e1, 0.f) - log1pf(__expf(-fabsf(e1)));
                }
                if (valid)
                    *reinterpret_cast<float2*>(&outp[(size_t)trow * TB + col]) =
                        make_float2(e0, e1);
                if (proj == 3) {
                    red0 += valid ? e0 : 0.f;
                    red1 += valid ? e1 : 0.f;
                } else if (proj == 2) {
                    red0 = valid ? fmaxf(red0, e0) : red0;
                    red1 = valid ? fmaxf(red1, e1) : red1;
                }
            }
            if (proj == 3) {                      // chunk sum of lf -> g_cs
#pragma unroll
                for (int off = 4; off <= 16; off <<= 1) {
                    red0 += __shfl_xor_sync(0xffffffffu, red0, off);
                    red1 += __shfl_xor_sync(0xffffffffu, red1, off);
                }
                int c = blockIdx.x * 8 + wm * 4 + mt;
                if (g == 0 && c < NCH) {
                    g_cs[c * TB + col]     = red0;
                    g_cs[c * TB + col + 1] = red1;
                }
            } else if (proj == 2) {               // chunk max of zi -> g_zmax
#pragma unroll
                for (int off = 4; off <= 16; off <<= 1) {
                    red0 = fmaxf(red0, __shfl_xor_sync(0xffffffffu, red0, off));
                    red1 = fmaxf(red1, __shfl_xor_sync(0xffffffffu, red1, off));
                }
                int c = blockIdx.x * 8 + wm * 4 + mt;
                if (g == 0 && c < NCH) {
                    g_zmax[c * TB + col]     = red0;
                    g_zmax[c * TB + col + 1] = red1;
                }
            }
        }
    }
}

// ---------------- 3. suffix over chunks: one BLOCK per b ----------------------
__global__ void __launch_bounds__(256)
s2_chunkscan() {
    const int b = blockIdx.x;
    const int t = threadIdx.x;
    __shared__ float sv[256];
    float v = (t < NCH) ? g_cs[t * TB + b] : 0.f;
    sv[t] = v;
    __syncthreads();
#pragma unroll
    for (int d = 1; d < 256; d <<= 1) {
        float add = (t + d < 256) ? sv[t + d] : 0.f;
        __syncthreads();
        sv[t] += add;
        __syncthreads();
    }
    if (t < NCH) {
        float run = (t + 1 < 256) ? sv[t + 1] : 0.f;  // exclusive suffix
        g_sfx[t * TB + b] = run;
    }
}

// ---------------- 4. contribs + w + partial dots (batched loads) --------------
__global__ void __launch_bounds__(TB)
s3_contrib() {
    const int b = threadIdx.x, c = blockIdx.x;
    const int wid = b >> 5, lid = b & 31;
    __shared__ float Cs[CH][TB + 1];
    __shared__ float ws[CH];

    float suffix = g_sfx[c * TB + b];
    float zm     = g_zmax[c * TB + b];
    bool live = (zm + suffix > -85.f);
    if (__syncthreads_or(live ? 1 : 0) == 0) {     // whole block dead
        g_part[c * TB + b] = 0.f;
        if (b == 0) g_wsum[c] = 0.f;
        return;
    }

    // front-batched independent loads
    const int tbase = c * CH;
    float zi_r[CH], kk_r[CH], lf_r[CH], vv_r[CH];
#pragma unroll
    for (int i = 0; i < CH; ++i) {
        int t = tbase + i;
        int tc = (t < TP) ? t : (TP - 1);
        size_t o = (size_t)tc * TB + b;
        zi_r[i] = g_zib[o];
        kk_r[i] = g_kb[o];
        lf_r[i] = g_lfb[o];
        vv_r[i] = g_vb[o];
    }

    float qb = g_qT[b];
    float run = suffix;
#pragma unroll
    for (int i = CH - 1; i >= 0; --i) {
        float cv = 0.f;
        if (tbase + i < TP) {
            if (live) {
                float zr = zi_r[i] + run;
                if (zr > -85.f) cv = __expf(zr) * kk_r[i] * qb;
            }
            run += lf_r[i];
        }
        Cs[i][b] = cv;
    }
    __syncthreads();
#pragma unroll
    for (int p = 0; p < 2; ++p) {
        int i = p * 12 + wid;
        if (i < CH) {
            float s = 0.f;
#pragma unroll
            for (int jj = lid; jj < TB; jj += 32) s += Cs[i][jj];
#pragma unroll
            for (int off = 16; off; off >>= 1) s += __shfl_xor_sync(0xffffffffu, s, off);
            if (lid == 0) ws[i] = s;
        }
    }
    __syncthreads();
    float pnum = 0.f;
#pragma unroll
    for (int i = 0; i < CH; ++i)
        if (tbase + i < TP) pnum = fmaf(vv_r[i], ws[i], pnum);
    g_part[c * TB + b] = pnum;
    if (b == 0) {
        float s = 0.f;
#pragma unroll
        for (int i = 0; i < CH; ++i) s += ws[i];
        g_wsum[c] = s;
    }
}

// ---------------- 5. combine: h[a] --------------------------------------------
__global__ void __launch_bounds__(TB)
f2_combine(float* __restrict__ out) {
    int a = threadIdx.x;
    float num = 0.f, den = 0.f;
#pragma unroll 8
    for (int c = 0; c < NCH; ++c) num += g_part[c * TB + a];
#pragma unroll 8
    for (int c = 0; c < NCH; ++c) den += g_wsum[c];
    out[a] = g_oT[a] * num / fmaxf(fabsf(den), 1.0f);
}

// -----------------------------------------------------------------------------
extern "C" void kernel_launch(void* const* d_in, const int* in_sizes, int n_in,
                              void* d_out, int out_size) {
    const float* x  = (const float*)d_in[0];
    const float* Wq = (const float*)d_in[1];  const float* bq = (const float*)d_in[2];
    const float* Wk = (const float*)d_in[3];  const float* bk = (const float*)d_in[4];
    const float* Wv = (const float*)d_in[5];  const float* bv = (const float*)d_in[6];
    const float* Wi = (const float*)d_in[7];  const float* bi = (const float*)d_in[8];
    const float* Wf = (const float*)d_in[9];  const float* bf = (const float*)d_in[10];
    const float* Wo = (const float*)d_in[11]; const float* bo = (const float*)d_in[12];
    const float* cw = (const float*)d_in[13]; const float* cb = (const float*)d_in[14];
    float* out = (float*)d_out;

    static int smem_set = 0;
    if (!smem_set) {
        cudaFuncSetAttribute(mma_gemm, cudaFuncAttributeMaxDynamicSharedMemorySize,
                             SMEM_GEMM);
        smem_set = 1;
    }

    prep<<<NB_CONV + NB_CVTB + NB_QO, 256>>>(x, cw, cb, Wq, bq, Wo, bo,
                                             Wk, Wv, Wi, Wf);
    mma_gemm<<<dim3(MPAD / 128, NTOT / 192), 384, SMEM_GEMM>>>(bk, bv, bi, bf);
    s2_chunkscan<<<TB, 256>>>();
    s3_contrib<<<NCH, TB>>>();
    f2_combine<<<1, TB>>>(out);
}